// round 17
// baseline (speedup 1.0000x reference)
#include <cuda_runtime.h>
#include <cuda_fp16.h>
#include <math.h>
#include <stdint.h>

// x[131072,256] @ W1[256,512] -> tanh -> @W2[512,512] -> tanh -> @W3[512,128] (+biases).
// Fixed-point loop converges to F(x) within ~4e-7 abs => output == MLP forward.
// Numerics (twice-calibrated): single-fp16 A and B, fp32 accum -> 5.045e-4.
// R17 = R13 (best, 474us) + L1 fuses the x fp32->fp16 conversion using cp.async
// staging (async, unlike R16's stalling LDG version). L2/L3 identical to R13.
constexpr int BATCH = 131072;
constexpr int DIN   = 256;
constexpr int HID   = 512;
constexpr int DOUT  = 128;

// ---------- device scratch (static; no runtime allocation allowed) ----------
__device__ __align__(256) __half g_h1[(size_t)BATCH * HID];
__device__ __align__(256) __half g_h2[(size_t)BATCH * HID];

constexpr size_t W1_OFF = 0;
constexpr size_t W1_SZ  = (size_t)HID * DIN;
constexpr size_t W2_OFF = W1_OFF + W1_SZ;
constexpr size_t W2_SZ  = (size_t)HID * HID;
constexpr size_t W3_OFF = W2_OFF + W2_SZ;
constexpr size_t W3_SZ  = (size_t)DOUT * HID;
__device__ __align__(256) __half g_w[W1_SZ + W2_SZ + W3_SZ];   // fp16 weights, [N,K] K-major

// ---------- PTX helpers (compute_103-safe: NO tcgen05) ----------
__device__ __forceinline__ uint32_t smem_u32(const void* p) {
    uint32_t a;
    asm("{ .reg .u64 t; cvta.to.shared.u64 t, %1; cvt.u32.u64 %0, t; }" : "=r"(a) : "l"(p));
    return a;
}
__device__ __forceinline__ void cp16(uint32_t dst, const void* src) {
    asm volatile("cp.async.cg.shared.global [%0], [%1], 16;" :: "r"(dst), "l"(src));
}
__device__ __forceinline__ void cp_commit() { asm volatile("cp.async.commit_group;"); }
__device__ __forceinline__ void cp_wait1()  { asm volatile("cp.async.wait_group 1;"); }

__device__ __forceinline__ void ldsm4(uint32_t* r, uint32_t addr) {
    asm volatile("ldmatrix.sync.aligned.m8n8.x4.shared.b16 {%0,%1,%2,%3}, [%4];"
                 : "=r"(r[0]), "=r"(r[1]), "=r"(r[2]), "=r"(r[3]) : "r"(addr));
}
__device__ __forceinline__ void mma16816(float* d, const uint32_t* a, const uint32_t* b) {
    asm volatile("mma.sync.aligned.m16n8k16.row.col.f32.f16.f16.f32 "
                 "{%0,%1,%2,%3}, {%4,%5,%6,%7}, {%8,%9}, {%0,%1,%2,%3};"
                 : "+f"(d[0]), "+f"(d[1]), "+f"(d[2]), "+f"(d[3])
                 : "r"(a[0]), "r"(a[1]), "r"(a[2]), "r"(a[3]), "r"(b[0]), "r"(b[1]));
}

// fast accurate tanh: (e-1)/(e+1), e = 2^(2x*log2e). abs err ~1e-7.
__device__ __forceinline__ float tanh_fast(float x) {
    float xc = fminf(fmaxf(x, -15.0f), 15.0f);
    float e;
    asm("ex2.approx.f32 %0, %1;" : "=f"(e) : "f"(xc * 2.885390081777927f));
    float r;
    asm("rcp.approx.f32 %0, %1;" : "=f"(r) : "f"(e + 1.0f));
    return (e - 1.0f) * r;
}

__device__ __forceinline__ uint32_t pack2h(float v0, float v1) {
    __half h0 = __float2half_rn(v0);
    __half h1 = __float2half_rn(v1);
    return (uint32_t)__half_as_ushort(h0) | ((uint32_t)__half_as_ushort(h1) << 16);
}

// ---------- prep: weights only (x conversion fused into L1) ----------
constexpr int WTOT = (int)(W1_SZ + W2_SZ + W3_SZ);                // 458752
constexpr int WB = (WTOT + 255) / 256;                            // 1792

__global__ void prep_w(const float* __restrict__ W1,
                       const float* __restrict__ W2,
                       const float* __restrict__ W3)
{
    int idx = blockIdx.x * 256 + threadIdx.x;
    if (idx >= WTOT) return;
    const float* W; int K, N, loc;
    if (idx < (int)W2_OFF)      { W = W1; K = DIN; N = HID;  loc = idx; }
    else if (idx < (int)W3_OFF) { W = W2; K = HID; N = HID;  loc = idx - (int)W2_OFF; }
    else                        { W = W3; K = HID; N = DOUT; loc = idx - (int)W3_OFF; }
    int n = loc / K;
    int k = loc - n * K;
    g_w[idx] = __float2half_rn(W[(size_t)k * N + n]);
}

// ---------- main GEMM: 128x128 tile, BK=32, 3-stage cp.async, single sync/iter ----------
// !AFP32 (L2/L3): exactly R13. SMEM = 3 x (A16 8KB | B 8KB) = 48KB.
// AFP32 (L1): A arrives as fp32 via cp.async into A32 staging; each thread LDS-reads
// the 64B it cp'd itself (self-visibility after wait_group), converts to fp16, STS
// into 2 ping-pong A16 buffers before the single barrier. SMEM = 2x8KB A16 +
// 3 x (A32 16KB | B 8KB) = 88KB. Both fit 2 CTAs/SM.
constexpr uint32_t OFF_A = 0;
constexpr uint32_t OFF_B = 8192;
constexpr uint32_t STAGE = 16384;
constexpr int SMEM_STD = 3 * STAGE;                 // 49152
// AFP32 layout
constexpr uint32_t F_A16_0   = 0;                   // two 8KB A16 buffers
constexpr uint32_t F_STAGE0  = 16384;               // stages: A32 16KB + B 8KB
constexpr uint32_t F_STAGE_SZ = 24576;
constexpr uint32_t F_B_OFF   = 16384;               // B offset within a stage
constexpr int SMEM_F = (int)(F_STAGE0 + 3 * F_STAGE_SZ);   // 90112

template<bool TANH, bool FP32OUT, bool AFP32>
__global__ __launch_bounds__(256, 2)
void gemm_hmma(const float* __restrict__ Xf, int aSel, size_t wOff,
               const float* __restrict__ bias,
               int cSel, float* __restrict__ Cf, int N, int K)
{
    const __half* A = (aSel == 1) ? g_h1 : g_h2;     // unused when AFP32
    __half* C = (cSel == 1) ? g_h1 : (cSel == 2) ? g_h2 : nullptr;
    const __half* W = g_w + wOff;

    extern __shared__ char smem[];
    const uint32_t sbase = smem_u32(smem);
    const int tid  = threadIdx.x;
    const int wid  = tid >> 5;
    const int lane = tid & 31;
    const int mBase = blockIdx.y * 128;
    const int nBase = blockIdx.x * 128;
    const int warpM = (wid >> 1) * 32;
    const int warpN = (wid & 1) * 64;
    const int NC = K / 32;

    // ---- fp16 loader mapping (A when !AFP32, B always) ----
    const int lr = tid >> 2;               // 0..63
    const int lj = tid & 3;
    const uint32_t swj = (uint32_t)lj * 16;
    auto so = [&](uint32_t row) { return row * 64 + (swj ^ ((row & 6) << 3)); };
    const uint32_t soA0 = so((uint32_t)lr), soA1 = so((uint32_t)(lr + 64));
    const size_t jcol = (size_t)lj * 8;
    const size_t gA0 = (size_t)(mBase + lr) * K + jcol;
    const size_t gA1 = (size_t)(mBase + lr + 64) * K + jcol;
    const size_t gB0 = (size_t)(nBase + lr) * K + jcol;
    const size_t gB1 = (size_t)(nBase + lr + 64) * K + jcol;

    // ---- AFP32 mappings: thread owns row (tid>>1), 16 fp32 cols ((tid&1)*16..+15) ----
    const int xr = tid >> 1;
    const int xh = tid & 1;
    const float* xsrc = AFP32 ? (Xf + (size_t)(mBase + xr) * K + xh * 16) : nullptr;
    // per-thread 64B slot in A32 staging; within-slot 16B rotation avoids bank pileup
    uint32_t a32off[4];
    #pragma unroll
    for (int i = 0; i < 4; i++)
        a32off[i] = (uint32_t)tid * 64 + ((((uint32_t)i + ((uint32_t)tid >> 3)) & 3) << 4);

    auto loadChunk = [&](int kc, int s) {
        if (AFP32) {
            const uint32_t sbS = sbase + F_STAGE0 + (uint32_t)s * F_STAGE_SZ;
            const float* p = xsrc + (size_t)kc * 32;
            #pragma unroll
            for (int i = 0; i < 4; i++)
                cp16(sbS + a32off[i], p + i * 4);
            const size_t co = (size_t)kc * 32;
            cp16(sbS + F_B_OFF + soA0, W + gB0 + co);
            cp16(sbS + F_B_OFF + soA1, W + gB1 + co);
        } else {
            const uint32_t sb = sbase + (uint32_t)s * STAGE;
            const size_t co = (size_t)kc * 32;
            cp16(sb + OFF_A + soA0, A + gA0 + co);
            cp16(sb + OFF_A + soA1, A + gA1 + co);
            cp16(sb + OFF_B + soA0, W + gB0 + co);
            cp16(sb + OFF_B + soA1, W + gB1 + co);
        }
    };

    auto convertA = [&](int c) {
        const uint32_t stg = F_STAGE0 + (uint32_t)(c % 3) * F_STAGE_SZ;
        float4 v[4];
        #pragma unroll
        for (int i = 0; i < 4; i++)
            v[i] = *reinterpret_cast<const float4*>(smem + stg + a32off[i]);
        uint4 o0, o1;
        o0.x = pack2h(v[0].x, v[0].y); o0.y = pack2h(v[0].z, v[0].w);
        o0.z = pack2h(v[1].x, v[1].y); o0.w = pack2h(v[1].z, v[1].w);
        o1.x = pack2h(v[2].x, v[2].y); o1.y = pack2h(v[2].z, v[2].w);
        o1.z = pack2h(v[3].x, v[3].y); o1.w = pack2h(v[3].z, v[3].w);
        const uint32_t dst = (uint32_t)(c & 1) * 8192;
        const uint32_t row = (uint32_t)xr;
        const uint32_t sw  = (row & 6) << 3;
        const uint32_t j0  = (uint32_t)xh * 2;
        *reinterpret_cast<uint4*>(smem + dst + row * 64 + ((j0 * 16) ^ sw))       = o0;
        *reinterpret_cast<uint4*>(smem + dst + row * 64 + (((j0 + 1) * 16) ^ sw)) = o1;
    };

    float acc[2][8][4];
    #pragma unroll
    for (int i = 0; i < 2; i++)
        #pragma unroll
        for (int j = 0; j < 8; j++)
            #pragma unroll
            for (int q = 0; q < 4; q++) acc[i][j][q] = 0.0f;

    const int lrow = lane & 15, lhi = lane >> 4;

    // hoisted fragment smem-offset components
    uint32_t aRow[2], aSw[2], bRow[4], bSw[4];
    #pragma unroll
    for (int i = 0; i < 2; i++) {
        uint32_t row = warpM + i * 16 + lrow;
        aRow[i] = row * 64; aSw[i] = (row & 6) << 3;
    }
    #pragma unroll
    for (int p = 0; p < 4; p++) {
        uint32_t row = warpN + p * 16 + lrow;
        bRow[p] = row * 64; bSw[p] = (row & 6) << 3;
    }

    loadChunk(0, 0); cp_commit();
    loadChunk(1, 1); cp_commit();

    for (int c = 0; c < NC; c++) {
        cp_wait1();                    // chunk c resident (self-visible for own cp data)
        if (AFP32) convertA(c);        // own-64B LDS -> cvt -> STS to A16 (c&1)
        __syncthreads();               // publish A16 + B; gate buffer reuse
        if (c + 2 < NC) loadChunk(c + 2, (c + 2) % 3);
        cp_commit();

        const uint32_t sbB = AFP32
            ? (sbase + F_STAGE0 + (uint32_t)(c % 3) * F_STAGE_SZ + F_B_OFF)
            : (sbase + (uint32_t)(c % 3) * STAGE + OFF_B);
        const uint32_t sbA = AFP32
            ? (sbase + (uint32_t)(c & 1) * 8192)
            : (sbase + (uint32_t)(c % 3) * STAGE + OFF_A);
        #pragma unroll
        for (int ks = 0; ks < 2; ks++) {
            const uint32_t colb = ks * 32 + lhi * 16;
            uint32_t ah[2][4], bb[8][2];
            #pragma unroll
            for (int i = 0; i < 2; i++) {
                uint32_t off = aRow[i] + (colb ^ aSw[i]);
                ldsm4(ah[i], sbA + off);
            }
            #pragma unroll
            for (int p = 0; p < 4; p++) {
                uint32_t off = bRow[p] + (colb ^ bSw[p]);
                uint32_t r[4];
                ldsm4(r, sbB + off);
                bb[2 * p][0] = r[0]; bb[2 * p][1] = r[2];
                bb[2 * p + 1][0] = r[1]; bb[2 * p + 1][1] = r[3];
            }
            #pragma unroll
            for (int i = 0; i < 2; i++)
                #pragma unroll
                for (int j = 0; j < 8; j++) mma16816(acc[i][j], ah[i], bb[j]);
        }
    }

    // ---------- epilogue ----------
    #pragma unroll
    for (int i = 0; i < 2; i++) {
        const int m0 = mBase + warpM + i * 16 + (lane >> 2);
        #pragma unroll
        for (int j = 0; j < 8; j++) {
            const int n = nBase + warpN + j * 8 + (lane & 3) * 2;
            const float2 bb2 = *reinterpret_cast<const float2*>(&bias[n]);
            float v00 = acc[i][j][0] + bb2.x, v01 = acc[i][j][1] + bb2.y;
            float v10 = acc[i][j][2] + bb2.x, v11 = acc[i][j][3] + bb2.y;
            if (TANH) {
                v00 = tanh_fast(v00); v01 = tanh_fast(v01);
                v10 = tanh_fast(v10); v11 = tanh_fast(v11);
            }
            if (FP32OUT) {
                *reinterpret_cast<float2*>(&Cf[(size_t)m0 * N + n])       = make_float2(v00, v01);
                *reinterpret_cast<float2*>(&Cf[(size_t)(m0 + 8) * N + n]) = make_float2(v10, v11);
            } else {
                *reinterpret_cast<uint32_t*>(&C[(size_t)m0 * N + n])       = pack2h(v00, v01);
                *reinterpret_cast<uint32_t*>(&C[(size_t)(m0 + 8) * N + n]) = pack2h(v10, v11);
            }
        }
    }
}

// ---------- launch ----------
extern "C" void kernel_launch(void* const* d_in, const int* in_sizes, int n_in,
                              void* d_out, int out_size)
{
    const float* x  = (const float*)d_in[0];
    const float* W1 = (const float*)d_in[1];
    const float* b1 = (const float*)d_in[2];
    const float* W2 = (const float*)d_in[3];
    const float* b2 = (const float*)d_in[4];
    const float* W3 = (const float*)d_in[5];
    const float* b3 = (const float*)d_in[6];
    float* out = (float*)d_out;

    prep_w<<<WB, 256>>>(W1, W2, W3);

    cudaFuncSetAttribute(gemm_hmma<true,  false, true >,
                         cudaFuncAttributeMaxDynamicSharedMemorySize, SMEM_F);
    cudaFuncSetAttribute(gemm_hmma<true,  false, false>,
                         cudaFuncAttributeMaxDynamicSharedMemorySize, SMEM_STD);
    cudaFuncSetAttribute(gemm_hmma<false, true,  false>,
                         cudaFuncAttributeMaxDynamicSharedMemorySize, SMEM_STD);

    dim3 grid12(HID / 128, BATCH / 128);   // (4, 1024)
    dim3 grid3 (DOUT / 128, BATCH / 128);  // (1, 1024)

    // L1: h1 = tanh(x(fp32) @ W1 + b1) — fused conversion, async staging
    gemm_hmma<true,  false, true ><<<grid12, 256, SMEM_F  >>>(x, 0, W1_OFF, b1, 1, nullptr, HID, DIN);
    // L2: h2 = tanh(h1 @ W2 + b2)
    gemm_hmma<true,  false, false><<<grid12, 256, SMEM_STD>>>(nullptr, 1, W2_OFF, b2, 2, nullptr, HID, HID);
    // L3: out = h2 @ W3 + b3
    gemm_hmma<false, true,  false><<<grid3,  256, SMEM_STD>>>(nullptr, 2, W3_OFF, b3, 0, out, DOUT, HID);
}